// round 13
// baseline (speedup 1.0000x reference)
#include <cuda_runtime.h>
#include <cuda_fp16.h>
#include <cstdint>

#define Hh   744
#define HP   768
#define Bb   256
#define Tt   256
#define Cc   16
#define WIN  800
#define TB   (Tt*Bb)          // 65536
#define OUTT (Tt - 2*Cc)      // 224
#define OUTW (2*Hh)           // 1488

#define NJT    32             // j-tiles per dir
#define JT     24             // j-cols per tile
#define NCTA   (2*NJT)        // 64 persistent CTAs
#define WS_STRIDE 776         // halfs: 768 + 8 pad
#define KC     64
#define NCH    (HP/KC)        // 12
#define PCHUNK 32768          // 256 rows x 128B
#define GCHUNK 16384          // 128 rows x 128B

// ---------------- scratch ----------------
__device__ __half g_Wic[6][NCH][HP][KC];
__device__ __half g_Wh16[2][3][HP][HP];
__device__ float  g_bi[2][3][HP];
__device__ float  g_bh[2][3][HP];
__device__ __half g_Xc[NCH][TB][KC];
__device__ float  g_GI[2][3][TB][HP];
__device__ __half g_hc[2][2][NCH][Bb][KC];    // [parity][dir][chunk][b][k] swizzled
__device__ unsigned g_hcnt[2][Tt + 1][NCH];   // h-chunk readiness (target 3 or 4)
__device__ unsigned g_ready[2][Tt];
__device__ unsigned g_pcnt[2][Tt];

// ---------------- helpers ----------------
__device__ __forceinline__ float sigf(float x) { return 1.0f / (1.0f + __expf(-x)); }
__device__ __forceinline__ float tanh_fast(float x) {
    x = fminf(15.0f, fmaxf(-15.0f, x));
    float e = __expf(2.0f * x);
    return (e - 1.0f) / (e + 1.0f);
}
__device__ __forceinline__ void mma_fp16(float* c, const uint32_t* a, const uint32_t* b) {
    asm volatile(
        "mma.sync.aligned.m16n8k16.row.col.f32.f16.f16.f32 "
        "{%0,%1,%2,%3},{%4,%5,%6,%7},{%8,%9},{%0,%1,%2,%3};\n"
        : "+f"(c[0]), "+f"(c[1]), "+f"(c[2]), "+f"(c[3])
        : "r"(a[0]), "r"(a[1]), "r"(a[2]), "r"(a[3]), "r"(b[0]), "r"(b[1]));
}
__device__ __forceinline__ uint32_t s2u(const void* p) {
    return (uint32_t)__cvta_generic_to_shared(p);
}
__device__ __forceinline__ void ldsm4(uint32_t* r, uint32_t addr) {
    asm volatile("ldmatrix.sync.aligned.m8n8.x4.shared.b16 {%0,%1,%2,%3}, [%4];"
        : "=r"(r[0]), "=r"(r[1]), "=r"(r[2]), "=r"(r[3]) : "r"(addr));
}
__device__ __forceinline__ void ldsm2(uint32_t* r, uint32_t addr) {
    asm volatile("ldmatrix.sync.aligned.m8n8.x2.shared.b16 {%0,%1}, [%2];"
        : "=r"(r[0]), "=r"(r[1]) : "r"(addr));
}
#define MBAR_INIT(addr, cnt) \
    asm volatile("mbarrier.init.shared.b64 [%0], %1;" :: "r"(addr), "r"(cnt) : "memory")
#define MBAR_WAIT(addr, par) do { \
    asm volatile("{.reg .pred P1; WL%=: mbarrier.try_wait.parity.acquire.cta.shared::cta.b64 P1, [%0], %1, 0x989680; @P1 bra.uni WD%=; bra.uni WL%=; WD%=:}" \
        :: "r"(addr), "r"(par) : "memory"); \
} while (0)
__device__ __forceinline__ void bulk_ld(uint32_t dst, const void* src, uint32_t bytes, uint32_t mb) {
    asm volatile("cp.async.bulk.shared::cta.global.mbarrier::complete_tx::bytes [%0], [%1], %2, [%3];"
        :: "r"(dst), "l"(src), "r"(bytes), "r"(mb) : "memory");
}
__device__ __forceinline__ void expect_tx(uint32_t mb, uint32_t bytes) {
    asm volatile("mbarrier.arrive.expect_tx.shared.b64 _, [%0], %1;"
        :: "r"(mb), "r"(bytes) : "memory");
}
__device__ __forceinline__ unsigned ld_acq(const unsigned* p) {
    unsigned v;
    asm volatile("ld.acquire.gpu.global.u32 %0, [%1];" : "=r"(v) : "l"(p));
    return v;
}

// ---------------- prep kernels ----------------
__global__ void prep_w(const float* __restrict__ Wih, const float* __restrict__ Whh,
                       const float* __restrict__ bih, const float* __restrict__ bhh, int d) {
    int idx = blockIdx.x * blockDim.x + threadIdx.x;
    const int total = 3 * HP * HP;
    if (idx < total) {
        int g = idx / (HP * HP);
        int rem = idx % (HP * HP);
        int j = rem / HP;
        int k = rem % HP;
        float wi = 0.0f, wh = 0.0f;
        if (j < Hh && k < Hh) {
            wi = Wih[(size_t)(g * Hh + j) * Hh + k];
            wh = Whh[(size_t)(g * Hh + j) * Hh + k];
        }
        int dg = d * 3 + g;
        int ch = k / KC, kc = k % KC;
        size_t off = (((size_t)dg * NCH + ch) * HP + j) * 128 + (((unsigned)(kc * 2)) ^ ((j & 7) << 4));
        *(__half*)((char*)g_Wic + off) = __float2half_rn(wi);
        g_Wh16[d][g][j][k] = __float2half_rn(wh);
    }
    if (idx < 3 * HP) {
        int g = idx / HP, j = idx % HP;
        float bi = 0.0f, bh = 0.0f;
        if (j < Hh) { bi = bih[g * Hh + j]; bh = bhh[g * Hh + j]; }
        g_bi[d][g][j] = bi;
        g_bh[d][g][j] = bh;
    }
}

__global__ void prep_x(const float* __restrict__ win) {
    int idx = blockIdx.x * blockDim.x + threadIdx.x;
    const int total = TB * (HP / 4);
    if (idx >= total) return;
    int row = idx / (HP / 4);
    int kq  = idx % (HP / 4);
    int k = kq * 4;
    int t = row / Bb, b = row % Bb;
    float4 v = make_float4(0.f, 0.f, 0.f, 0.f);
    if (k < Hh) {
        v = *(const float4*)(win + (size_t)b * Tt * WIN + (size_t)t * WIN + k);
    }
    int ch = k / KC, kc = k % KC;
    size_t off = ((size_t)ch * TB + row) * 128 + (((unsigned)(kc * 2)) ^ ((row & 7) << 4));
    __half2* dst = (__half2*)((char*)g_Xc + off);
    dst[0] = __floats2half2_rn(v.x, v.y);
    dst[1] = __floats2half2_rn(v.z, v.w);
}

__global__ void zero_h() {
    int idx = blockIdx.x * blockDim.x + threadIdx.x;
    const int hcu32 = 2 * 2 * NCH * Bb * KC / 2;
    if (idx < hcu32) ((uint32_t*)g_hc)[idx] = 0u;
    const int hcnt_total = 2 * (Tt + 1) * NCH;
    if (idx < hcnt_total) {
        int within = idx % ((Tt + 1) * NCH);
        int step = within / NCH;
        int c = within % NCH;
        unsigned tgt = (c % 3 == 1) ? 4u : 3u;
        ((unsigned*)g_hcnt)[idx] = (step == 0) ? tgt : 0u;
    }
    if (idx < 2 * Tt) { ((unsigned*)g_ready)[idx] = 0u; ((unsigned*)g_pcnt)[idx] = 0u; }
}

// ---------------- K1: GI = X @ Wih^T + bih (all planes, outward-in order) ----------------
#define GI_SMEM (1024 + 4 * GCHUNK)
__global__ void __launch_bounds__(256, 2) k_gi() {
    extern __shared__ __align__(1024) char smem[];
    const uint32_t sb = s2u(smem);

    const int tid  = threadIdx.x;
    const int lane = tid & 31;
    const int w    = tid >> 5;
    const int grp  = lane >> 2;
    const int tg   = lane & 3;
    const int wm   = w >> 1;
    const int wn   = w & 1;

    const int bx  = blockIdx.x;
    const int d   = bx / 18;
    const int rem = bx % 18;
    const int g   = rem / 6;
    const int nt  = rem % 6;
    const int j0  = nt * 128;
    const int dg  = d * 3 + g;

    const int ti    = blockIdx.y >> 1;
    const int halfb = blockIdx.y & 1;
    const int t     = (ti & 1) ? (Tt - 1 - (ti >> 1)) : (ti >> 1);
    const int row0  = t * Bb + halfb * 128;

    if (tid == 0) { MBAR_INIT(sb, 1); MBAR_INIT(sb + 8, 1); }
    __syncthreads();

    const int arow  = wm * 32 + (lane & 15);
    const uint32_t arb  = (uint32_t)arow * 128;
    const uint32_t axor = (uint32_t)(arow & 7) << 4;
    const uint32_t acl  = (uint32_t)(lane >> 4) << 4;
    const int brow  = wn * 64 + (lane >> 4) * 8 + (lane & 7);
    const uint32_t brb  = (uint32_t)brow * 128;
    const uint32_t bxor = (uint32_t)(brow & 7) << 4;
    const uint32_t bcl  = (uint32_t)((lane >> 3) & 1) << 4;

    float acc[8][2][4];
#pragma unroll
    for (int nf = 0; nf < 8; nf++)
#pragma unroll
        for (int mi = 0; mi < 2; mi++)
#pragma unroll
            for (int i = 0; i < 4; i++) acc[nf][mi][i] = 0.0f;

    auto issue = [&](int c) {
        if (tid == 0) {
            const int s = c & 1;
            const uint32_t mb = sb + s * 8;
            expect_tx(mb, 2 * GCHUNK);
            bulk_ld(sb + 1024 + s * 2 * GCHUNK,
                    (const char*)g_Xc + ((size_t)c * TB + row0) * 128, GCHUNK, mb);
            bulk_ld(sb + 1024 + s * 2 * GCHUNK + GCHUNK,
                    (const char*)g_Wic + (((size_t)dg * NCH + c) * HP + j0) * 128, GCHUNK, mb);
        }
    };

    int ph[2] = {0, 0};
    issue(0);

    for (int kt = 0; kt < NCH; kt++) {
        const int s = kt & 1;
        if (kt < NCH - 1) issue(kt + 1);
        MBAR_WAIT(sb + s * 8, ph[s]);
        ph[s] ^= 1;

        const uint32_t abuf = sb + 1024 + s * 2 * GCHUNK;
        const uint32_t bbuf = abuf + GCHUNK;
#pragma unroll
        for (int kk = 0; kk < 4; kk++) {
            const uint32_t ac = ((uint32_t)(kk * 32) + acl) ^ axor;
            const uint32_t bc = ((uint32_t)(kk * 32) + bcl) ^ bxor;
            uint32_t af[2][4];
            ldsm4(af[0], abuf + arb + ac);
            ldsm4(af[1], abuf + arb + 2048 + ac);
#pragma unroll
            for (int p = 0; p < 4; p++) {
                uint32_t bf[4];
                ldsm4(bf, bbuf + brb + p * 2048 + bc);
                mma_fp16(acc[2 * p][0],     af[0], bf);
                mma_fp16(acc[2 * p][1],     af[1], bf);
                mma_fp16(acc[2 * p + 1][0], af[0], bf + 2);
                mma_fp16(acc[2 * p + 1][1], af[1], bf + 2);
            }
        }
        __syncthreads();
    }

    float* __restrict__ GIp = &g_GI[d][g][0][0];
    const float* __restrict__ bip = &g_bi[d][g][0];
#pragma unroll
    for (int mi = 0; mi < 2; mi++) {
#pragma unroll
        for (int nf = 0; nf < 8; nf++) {
            int r = row0 + wm * 32 + mi * 16 + grp;
            int j = j0 + wn * 64 + nf * 8 + tg * 2;
            float b0 = bip[j], b1 = bip[j + 1];
            float* a = acc[nf][mi];
            GIp[(size_t)r * HP + j]           = a[0] + b0;
            GIp[(size_t)r * HP + j + 1]       = a[1] + b1;
            GIp[(size_t)(r + 8) * HP + j]     = a[2] + b0;
            GIp[(size_t)(r + 8) * HP + j + 1] = a[3] + b1;
        }
    }

    __threadfence();
    __syncthreads();
    if (tid == 0) {
        unsigned old = atomicAdd(&g_pcnt[d][t], 1u);
        if (old == 35u) {
            asm volatile("st.release.gpu.global.u32 [%0], %1;"
                         :: "l"(&g_ready[d][t]), "r"(1u) : "memory");
        }
    }
}

// ---------------- persistent recurrent kernel (JT=24, 64 CTAs) ----------------
// smem: mbar0/1 @0/8 | 1024: A stages 2x32KB | 66560: Ws 72x776 halfs (111744) => 178304
#define P_ABUF  1024
#define P_WSOFF (P_ABUF + 2 * PCHUNK)
#define P_SMEM  (P_WSOFF + 72 * WS_STRIDE * 2)
__global__ void __launch_bounds__(256, 1)
k_persist(const float* __restrict__ win, float* __restrict__ out) {
    extern __shared__ __align__(1024) char smem[];
    const uint32_t sb = s2u(smem);
    __half* Ws = (__half*)(smem + P_WSOFF);

    const int tid  = threadIdx.x;
    const int lane = tid & 31;
    const int w    = tid >> 5;
    const int grp  = lane >> 2;
    const int tg   = lane & 3;
    const int m0w  = w * 32;

    const int d    = blockIdx.x / NJT;
    const int j0   = (blockIdx.x % NJT) * JT;
    const int c0   = j0 >> 6;
    const int c1   = (j0 + JT - 1) >> 6;

    if (tid == 0) { MBAR_INIT(sb, 1); MBAR_INIT(sb + 8, 1); }

    // resident weights: Ws[c][k], c = g*24 + jj (72 rows x 768 halfs)
    {
        const __half* src = &g_Wh16[d][0][0][0];
        for (int idx = tid; idx < 72 * (HP / 8); idx += 256) {
            int c = idx / (HP / 8);
            int k8 = (idx % (HP / 8)) * 8;
            int g = c / JT, jj = c % JT;
            *(uint4*)&Ws[c * WS_STRIDE + k8] =
                *(const uint4*)(src + ((size_t)g * HP + (j0 + jj)) * HP + k8);
        }
    }
    __syncthreads();

    const int arow  = m0w + (lane & 15);
    const uint32_t arb  = (uint32_t)arow * 128;
    const uint32_t axor = (uint32_t)(arow & 7) << 4;
    const uint32_t acl  = (uint32_t)(lane >> 4) << 4;

    const int b_row  = (lane >> 4) * 8 + (lane & 7);
    const int b_koff = ((lane >> 3) & 1) * 8;
    uint32_t wsp4[4];
#pragma unroll
    for (int p = 0; p < 4; p++)
        wsp4[p] = s2u(Ws) + ((p * 16 + b_row) * WS_STRIDE + b_koff) * 2;
    const uint32_t wsp2 = s2u(Ws) + ((64 + (lane & 7)) * WS_STRIDE + b_koff) * 2;

    const size_t PLANE = (size_t)TB * HP;
    const float* __restrict__ GI0 = &g_GI[d][0][0][0];
    const float* __restrict__ bh0 = &g_bh[d][0][0];

    int ph[2] = {0, 0};
    float hreg[24];
#pragma unroll
    for (int i = 0; i < 24; i++) hreg[i] = 0.0f;

    for (int t = 0; t < Tt; t++) {
        const int p  = t & 1;
        const int xt = (d == 0) ? t : (Tt - 1 - t);
        const char* hcbase = (const char*)&g_hc[p][d][0][0][0];

        float acc[9][2][4];
#pragma unroll
        for (int nf = 0; nf < 9; nf++)
#pragma unroll
            for (int mi = 0; mi < 2; mi++)
#pragma unroll
                for (int i = 0; i < 4; i++) acc[nf][mi][i] = 0.0f;

        int nextI = 0;
        for (int kt = 0; kt < NCH; kt++) {
            while (nextI < NCH && nextI <= kt + 1) {
                if (tid == 0) {
                    const unsigned tgt = (nextI % 3 == 1) ? 4u : 3u;
                    const unsigned* cp = &g_hcnt[d][t][nextI];
                    while (ld_acq(cp) < tgt) __nanosleep(60);
                    const int st = nextI & 1;
                    const uint32_t mb = sb + st * 8;
                    expect_tx(mb, PCHUNK);
                    bulk_ld(sb + P_ABUF + st * PCHUNK,
                            hcbase + (size_t)nextI * PCHUNK, PCHUNK, mb);
                }
                nextI++;
            }
            const int st = kt & 1;
            MBAR_WAIT(sb + st * 8, ph[st]);
            ph[st] ^= 1;

            const uint32_t abuf = sb + P_ABUF + st * PCHUNK;
            const int k0 = kt * KC;
#pragma unroll
            for (int kk = 0; kk < 4; kk++) {
                const uint32_t ac = ((uint32_t)(kk * 32) + acl) ^ axor;
                uint32_t af0[4], af1[4];
                ldsm4(af0, abuf + arb + ac);
                ldsm4(af1, abuf + arb + 2048 + ac);
                const uint32_t col = (uint32_t)(k0 + kk * 16) * 2;
#pragma unroll
                for (int gq = 0; gq < 4; gq++) {
                    uint32_t bf[4];
                    ldsm4(bf, wsp4[gq] + col);
                    mma_fp16(acc[2 * gq][0],     af0, bf);
                    mma_fp16(acc[2 * gq][1],     af1, bf);
                    mma_fp16(acc[2 * gq + 1][0], af0, bf + 2);
                    mma_fp16(acc[2 * gq + 1][1], af1, bf + 2);
                }
                uint32_t bf2[2];
                ldsm2(bf2, wsp2 + col);
                mma_fp16(acc[8][0], af0, bf2);
                mma_fp16(acc[8][1], af1, bf2);
            }
            __syncthreads();
        }

        // wait for this step's GI plane
        if (tid == 0) {
            while (ld_acq(&g_ready[d][xt]) == 0u) __nanosleep(100);
        }
        __syncthreads();

        // ---- fused GRU epilogue (h state in registers) ----
        const bool doOut = (t >= Cc) && (t < Tt - Cc);
        char* __restrict__ hco = (char*)&g_hc[p ^ 1][d][0][0][0];

#pragma unroll
        for (int mi = 0; mi < 2; mi++) {
#pragma unroll
            for (int o = 0; o < 3; o++) {
                const int jj = o * 8 + tg * 2;
                const int j  = j0 + jj;
                const int cj = j >> 6;
                const int jc = j & 63;
                const float br0 = bh0[j],            br1 = bh0[j + 1];
                const float bz0 = bh0[HP + j],       bz1 = bh0[HP + j + 1];
                const float bn0 = bh0[2 * HP + j],   bn1 = bh0[2 * HP + j + 1];
#pragma unroll
                for (int hf = 0; hf < 2; hf++) {
                    const int unit = ((mi * 3 + o) * 2 + hf) * 2;
                    const int b  = m0w + mi * 16 + grp + hf * 8;
                    const int ai = hf * 2;
                    const float aR0 = acc[o][mi][ai],     aR1 = acc[o][mi][ai + 1];
                    const float aZ0 = acc[3 + o][mi][ai], aZ1 = acc[3 + o][mi][ai + 1];
                    const float aN0 = acc[6 + o][mi][ai], aN1 = acc[6 + o][mi][ai + 1];

                    const size_t gio = (size_t)(xt * Bb + b) * HP + j;
                    const float gr0 = __ldcg(&GI0[gio]);
                    const float gr1 = __ldcg(&GI0[gio + 1]);
                    const float gz0 = __ldcg(&GI0[PLANE + gio]);
                    const float gz1 = __ldcg(&GI0[PLANE + gio + 1]);
                    const float gn0 = __ldcg(&GI0[2 * PLANE + gio]);
                    const float gn1 = __ldcg(&GI0[2 * PLANE + gio + 1]);

                    const float ho0 = hreg[unit];
                    const float ho1 = hreg[unit + 1];

                    const float r0 = sigf(gr0 + aR0 + br0);
                    const float r1 = sigf(gr1 + aR1 + br1);
                    const float z0 = sigf(gz0 + aZ0 + bz0);
                    const float z1 = sigf(gz1 + aZ1 + bz1);
                    const float n0 = tanh_fast(gn0 + r0 * (aN0 + bn0));
                    const float n1 = tanh_fast(gn1 + r1 * (aN1 + bn1));
                    const float h0 = (1.0f - z0) * n0 + z0 * ho0;
                    const float h1 = (1.0f - z1) * n1 + z1 * ho1;

                    hreg[unit]     = h0;
                    hreg[unit + 1] = h1;

                    size_t hoff = (size_t)cj * PCHUNK + (size_t)b * 128
                                + ((unsigned)(jc * 2) ^ ((b & 7) << 4));
                    *(__half2*)(hco + hoff) = __floats2half2_rn(h0, h1);

                    if (doOut && j < Hh) {
                        const size_t xo = (size_t)b * Tt * WIN + (size_t)xt * WIN + j;
                        const size_t oo = (size_t)b * (OUTT * OUTW) + (size_t)(t - Cc) * OUTW + d * Hh + j;
                        out[oo]     = h0 + win[xo];
                        out[oo + 1] = h1 + win[xo + 1];
                    }
                }
            }
        }

        // publish own h-chunk contributions for step t+1 (tile may straddle 2 chunks)
        __threadfence();
        __syncthreads();
        if (tid == 0) {
            asm volatile("red.release.gpu.global.add.u32 [%0], 1;"
                         :: "l"(&g_hcnt[d][t + 1][c0]) : "memory");
            if (c1 != c0) {
                asm volatile("red.release.gpu.global.add.u32 [%0], 1;"
                             :: "l"(&g_hcnt[d][t + 1][c1]) : "memory");
            }
        }
    }
}

// ---------------- launch ----------------
extern "C" void kernel_launch(void* const* d_in, const int* in_sizes, int n_in,
                              void* d_out, int out_size) {
    const float* windows = (const float*)d_in[0];
    const float* Wih_f   = (const float*)d_in[1];
    const float* Whh_f   = (const float*)d_in[2];
    const float* bih_f   = (const float*)d_in[3];
    const float* bhh_f   = (const float*)d_in[4];
    const float* Wih_b   = (const float*)d_in[5];
    const float* Whh_b   = (const float*)d_in[6];
    const float* bih_b   = (const float*)d_in[7];
    const float* bhh_b   = (const float*)d_in[8];
    float* out = (float*)d_out;

    static cudaStream_t s2 = nullptr;
    static cudaEvent_t  eA = nullptr, eB = nullptr;
    static int init_done = 0;
    if (!init_done) {
        cudaFuncSetAttribute(k_persist, cudaFuncAttributeMaxDynamicSharedMemorySize, P_SMEM);
        cudaFuncSetAttribute(k_gi, cudaFuncAttributeMaxDynamicSharedMemorySize, GI_SMEM);
        cudaStreamCreateWithFlags(&s2, cudaStreamNonBlocking);
        cudaEventCreateWithFlags(&eA, cudaEventDisableTiming);
        cudaEventCreateWithFlags(&eB, cudaEventDisableTiming);
        init_done = 1;
    }

    // side stream: x staging (only k_gi consumes it)
    const int xtotal = TB * (HP / 4);
    prep_x<<<(xtotal + 255) / 256, 256, 0, s2>>>(windows);

    // main stream: weights + state init
    const int wthreads = 256;
    const int wtotal = 3 * HP * HP;
    prep_w<<<(wtotal + wthreads - 1) / wthreads, wthreads>>>(Wih_f, Whh_f, bih_f, bhh_f, 0);
    prep_w<<<(wtotal + wthreads - 1) / wthreads, wthreads>>>(Wih_b, Whh_b, bih_b, bhh_b, 1);
    const int ztotal = 2 * 2 * NCH * Bb * KC / 2;
    zero_h<<<(ztotal + 255) / 256, 256>>>();

    cudaEventRecord(eA, 0);

    // persist FIRST (64 CTAs, occupancy 1, 178KB smem)
    k_persist<<<NCTA, 256, P_SMEM>>>(windows, out);

    // helper on the 84 free SMs (x2 occupancy)
    cudaStreamWaitEvent(s2, eA, 0);
    k_gi<<<dim3(36, 512), 256, GI_SMEM, s2>>>();
    cudaEventRecord(eB, s2);

    cudaStreamWaitEvent(0, eB, 0);
}

// round 14
// speedup vs baseline: 1.0722x; 1.0722x over previous
#include <cuda_runtime.h>
#include <cuda_fp16.h>
#include <cstdint>

#define Hh   744
#define HP   768
#define Bb   256
#define Tt   256
#define Cc   16
#define WIN  800
#define TB   (Tt*Bb)          // 65536
#define OUTT (Tt - 2*Cc)      // 224
#define OUTW (2*Hh)           // 1488

#define NJT    48
#define JT     16
#define NCTA   (2*NJT)
#define WS_STRIDE 776         // halfs: 768 + 8 pad
#define KC     64
#define NCH    (HP/KC)        // 12
#define PCHUNK 32768          // 256 rows x 128B
#define GCHUNK 16384          // 128 rows x 128B
#define HEADB  96             // head-start buffer (steps, both dirs)

// ---------------- scratch ----------------
__device__ __half g_Wic[6][NCH][HP][KC];
__device__ __half g_Wh16[2][3][HP][HP];
__device__ float  g_bi[2][3][HP];
__device__ float  g_bh[2][3][HP];
__device__ __half g_Xc[NCH][TB][KC];
__device__ float  g_GI[2][3][TB][HP];
__device__ __half g_hc[2][2][NCH][Bb][KC];    // [parity][dir][chunk][b][k] swizzled
__device__ unsigned g_hcnt[2][Tt + 1][NCH];   // h-chunk readiness (target 4)
__device__ unsigned g_ready[2][Tt];
__device__ unsigned g_pcnt[2][Tt];

// ---------------- helpers ----------------
__device__ __forceinline__ float sigf(float x) { return 1.0f / (1.0f + __expf(-x)); }
__device__ __forceinline__ float tanh_fast(float x) {
    x = fminf(15.0f, fmaxf(-15.0f, x));
    float e = __expf(2.0f * x);
    return (e - 1.0f) / (e + 1.0f);
}
__device__ __forceinline__ void mma_fp16(float* c, const uint32_t* a, const uint32_t* b) {
    asm volatile(
        "mma.sync.aligned.m16n8k16.row.col.f32.f16.f16.f32 "
        "{%0,%1,%2,%3},{%4,%5,%6,%7},{%8,%9},{%0,%1,%2,%3};\n"
        : "+f"(c[0]), "+f"(c[1]), "+f"(c[2]), "+f"(c[3])
        : "r"(a[0]), "r"(a[1]), "r"(a[2]), "r"(a[3]), "r"(b[0]), "r"(b[1]));
}
__device__ __forceinline__ uint32_t s2u(const void* p) {
    return (uint32_t)__cvta_generic_to_shared(p);
}
__device__ __forceinline__ void ldsm4(uint32_t* r, uint32_t addr) {
    asm volatile("ldmatrix.sync.aligned.m8n8.x4.shared.b16 {%0,%1,%2,%3}, [%4];"
        : "=r"(r[0]), "=r"(r[1]), "=r"(r[2]), "=r"(r[3]) : "r"(addr));
}
#define MBAR_INIT(addr, cnt) \
    asm volatile("mbarrier.init.shared.b64 [%0], %1;" :: "r"(addr), "r"(cnt) : "memory")
#define MBAR_WAIT(addr, par) do { \
    asm volatile("{.reg .pred P1; WL%=: mbarrier.try_wait.parity.acquire.cta.shared::cta.b64 P1, [%0], %1, 0x989680; @P1 bra.uni WD%=; bra.uni WL%=; WD%=:}" \
        :: "r"(addr), "r"(par) : "memory"); \
} while (0)
__device__ __forceinline__ void bulk_ld(uint32_t dst, const void* src, uint32_t bytes, uint32_t mb) {
    asm volatile("cp.async.bulk.shared::cta.global.mbarrier::complete_tx::bytes [%0], [%1], %2, [%3];"
        :: "r"(dst), "l"(src), "r"(bytes), "r"(mb) : "memory");
}
__device__ __forceinline__ void expect_tx(uint32_t mb, uint32_t bytes) {
    asm volatile("mbarrier.arrive.expect_tx.shared.b64 _, [%0], %1;"
        :: "r"(mb), "r"(bytes) : "memory");
}
__device__ __forceinline__ unsigned ld_acq(const unsigned* p) {
    unsigned v;
    asm volatile("ld.acquire.gpu.global.u32 %0, [%1];" : "=r"(v) : "l"(p));
    return v;
}

// ---------------- prep kernels ----------------
__global__ void prep_w(const float* __restrict__ Wih, const float* __restrict__ Whh,
                       const float* __restrict__ bih, const float* __restrict__ bhh, int d) {
    int idx = blockIdx.x * blockDim.x + threadIdx.x;
    const int total = 3 * HP * HP;
    if (idx < total) {
        int g = idx / (HP * HP);
        int rem = idx % (HP * HP);
        int j = rem / HP;
        int k = rem % HP;
        float wi = 0.0f, wh = 0.0f;
        if (j < Hh && k < Hh) {
            wi = Wih[(size_t)(g * Hh + j) * Hh + k];
            wh = Whh[(size_t)(g * Hh + j) * Hh + k];
        }
        int dg = d * 3 + g;
        int ch = k / KC, kc = k % KC;
        size_t off = (((size_t)dg * NCH + ch) * HP + j) * 128 + (((unsigned)(kc * 2)) ^ ((j & 7) << 4));
        *(__half*)((char*)g_Wic + off) = __float2half_rn(wi);
        g_Wh16[d][g][j][k] = __float2half_rn(wh);
    }
    if (idx < 3 * HP) {
        int g = idx / HP, j = idx % HP;
        float bi = 0.0f, bh = 0.0f;
        if (j < Hh) { bi = bih[g * Hh + j]; bh = bhh[g * Hh + j]; }
        g_bi[d][g][j] = bi;
        g_bh[d][g][j] = bh;
    }
}

__global__ void prep_x(const float* __restrict__ win) {
    int idx = blockIdx.x * blockDim.x + threadIdx.x;
    const int total = TB * (HP / 4);
    if (idx >= total) return;
    int row = idx / (HP / 4);
    int kq  = idx % (HP / 4);
    int k = kq * 4;
    int t = row / Bb, b = row % Bb;
    float4 v = make_float4(0.f, 0.f, 0.f, 0.f);
    if (k < Hh) {
        v = *(const float4*)(win + (size_t)b * Tt * WIN + (size_t)t * WIN + k);
    }
    int ch = k / KC, kc = k % KC;
    size_t off = ((size_t)ch * TB + row) * 128 + (((unsigned)(kc * 2)) ^ ((row & 7) << 4));
    __half2* dst = (__half2*)((char*)g_Xc + off);
    dst[0] = __floats2half2_rn(v.x, v.y);
    dst[1] = __floats2half2_rn(v.z, v.w);
}

__global__ void zero_h() {
    int idx = blockIdx.x * blockDim.x + threadIdx.x;
    const int hcu32 = 2 * 2 * NCH * Bb * KC / 2;
    if (idx < hcu32) ((uint32_t*)g_hc)[idx] = 0u;
    const int hcnt_total = 2 * (Tt + 1) * NCH;
    if (idx < hcnt_total) {
        int within = idx % ((Tt + 1) * NCH);
        int step = within / NCH;
        ((unsigned*)g_hcnt)[idx] = (step == 0) ? 4u : 0u;
    }
    if (idx < 2 * Tt) { ((unsigned*)g_ready)[idx] = 0u; ((unsigned*)g_pcnt)[idx] = 0u; }
}

// ---------------- K1: GI = X @ Wih^T + bih ----------------
// grid (18, ny): x = g*6 + nt; y+ybase encodes (plane-order e, half):
//   e = y>>1, half = y&1; d = e&1; tc = e>>1; t = d ? Tt-1-tc : tc
// -> planes produced in exact cross-direction consumption order.
#define GI_SMEM (1024 + 4 * GCHUNK)
__global__ void __launch_bounds__(256, 2) k_gi(int ybase) {
    extern __shared__ __align__(1024) char smem[];
    const uint32_t sb = s2u(smem);

    const int tid  = threadIdx.x;
    const int lane = tid & 31;
    const int w    = tid >> 5;
    const int grp  = lane >> 2;
    const int tg   = lane & 3;
    const int wm   = w >> 1;
    const int wn   = w & 1;

    const int bx  = blockIdx.x;
    const int g   = bx / 6;
    const int nt  = bx % 6;
    const int j0  = nt * 128;

    const int y     = ybase + blockIdx.y;
    const int e     = y >> 1;
    const int halfb = y & 1;
    const int d     = e & 1;
    const int tc    = e >> 1;
    const int t     = d ? (Tt - 1 - tc) : tc;
    const int dg    = d * 3 + g;
    const int row0  = t * Bb + halfb * 128;

    if (tid == 0) { MBAR_INIT(sb, 1); MBAR_INIT(sb + 8, 1); }
    __syncthreads();

    const int arow  = wm * 32 + (lane & 15);
    const uint32_t arb  = (uint32_t)arow * 128;
    const uint32_t axor = (uint32_t)(arow & 7) << 4;
    const uint32_t acl  = (uint32_t)(lane >> 4) << 4;
    const int brow  = wn * 64 + (lane >> 4) * 8 + (lane & 7);
    const uint32_t brb  = (uint32_t)brow * 128;
    const uint32_t bxor = (uint32_t)(brow & 7) << 4;
    const uint32_t bcl  = (uint32_t)((lane >> 3) & 1) << 4;

    float acc[8][2][4];
#pragma unroll
    for (int nf = 0; nf < 8; nf++)
#pragma unroll
        for (int mi = 0; mi < 2; mi++)
#pragma unroll
            for (int i = 0; i < 4; i++) acc[nf][mi][i] = 0.0f;

    auto issue = [&](int c) {
        if (tid == 0) {
            const int s = c & 1;
            const uint32_t mb = sb + s * 8;
            expect_tx(mb, 2 * GCHUNK);
            bulk_ld(sb + 1024 + s * 2 * GCHUNK,
                    (const char*)g_Xc + ((size_t)c * TB + row0) * 128, GCHUNK, mb);
            bulk_ld(sb + 1024 + s * 2 * GCHUNK + GCHUNK,
                    (const char*)g_Wic + (((size_t)dg * NCH + c) * HP + j0) * 128, GCHUNK, mb);
        }
    };

    int ph[2] = {0, 0};
    issue(0);

    for (int kt = 0; kt < NCH; kt++) {
        const int s = kt & 1;
        if (kt < NCH - 1) issue(kt + 1);
        MBAR_WAIT(sb + s * 8, ph[s]);
        ph[s] ^= 1;

        const uint32_t abuf = sb + 1024 + s * 2 * GCHUNK;
        const uint32_t bbuf = abuf + GCHUNK;
#pragma unroll
        for (int kk = 0; kk < 4; kk++) {
            const uint32_t ac = ((uint32_t)(kk * 32) + acl) ^ axor;
            const uint32_t bc = ((uint32_t)(kk * 32) + bcl) ^ bxor;
            uint32_t af[2][4];
            ldsm4(af[0], abuf + arb + ac);
            ldsm4(af[1], abuf + arb + 2048 + ac);
#pragma unroll
            for (int p = 0; p < 4; p++) {
                uint32_t bf[4];
                ldsm4(bf, bbuf + brb + p * 2048 + bc);
                mma_fp16(acc[2 * p][0],     af[0], bf);
                mma_fp16(acc[2 * p][1],     af[1], bf);
                mma_fp16(acc[2 * p + 1][0], af[0], bf + 2);
                mma_fp16(acc[2 * p + 1][1], af[1], bf + 2);
            }
        }
        __syncthreads();
    }

    float* __restrict__ GIp = &g_GI[d][g][0][0];
    const float* __restrict__ bip = &g_bi[d][g][0];
#pragma unroll
    for (int mi = 0; mi < 2; mi++) {
#pragma unroll
        for (int nf = 0; nf < 8; nf++) {
            int r = row0 + wm * 32 + mi * 16 + grp;
            int j = j0 + wn * 64 + nf * 8 + tg * 2;
            float b0 = bip[j], b1 = bip[j + 1];
            float* a = acc[nf][mi];
            GIp[(size_t)r * HP + j]           = a[0] + b0;
            GIp[(size_t)r * HP + j + 1]       = a[1] + b1;
            GIp[(size_t)(r + 8) * HP + j]     = a[2] + b0;
            GIp[(size_t)(r + 8) * HP + j + 1] = a[3] + b1;
        }
    }

    __threadfence();
    __syncthreads();
    if (tid == 0) {
        unsigned old = atomicAdd(&g_pcnt[d][t], 1u);
        if (old == 35u) {
            asm volatile("st.release.gpu.global.u32 [%0], %1;"
                         :: "l"(&g_ready[d][t]), "r"(1u) : "memory");
        }
    }
}

// ---------------- persistent recurrent kernel (R11, unchanged) ----------------
// smem: mbar0/1 @0/8 | 1024: A stages 2x32KB | 66560: Ws (74496) => 141056
#define P_ABUF  1024
#define P_WSOFF (P_ABUF + 2 * PCHUNK)
#define P_SMEM  (P_WSOFF + 48 * WS_STRIDE * 2)
__global__ void __launch_bounds__(256, 2)
k_persist(const float* __restrict__ win, float* __restrict__ out) {
    extern __shared__ __align__(1024) char smem[];
    const uint32_t sb = s2u(smem);
    __half* Ws = (__half*)(smem + P_WSOFF);

    const int tid  = threadIdx.x;
    const int lane = tid & 31;
    const int w    = tid >> 5;
    const int grp  = lane >> 2;
    const int tg   = lane & 3;
    const int m0w  = w * 32;

    const int d    = blockIdx.x / NJT;
    const int j0   = (blockIdx.x % NJT) * JT;
    const int chnk = j0 >> 6;

    if (tid == 0) { MBAR_INIT(sb, 1); MBAR_INIT(sb + 8, 1); }

    {
        const __half* src = &g_Wh16[d][0][0][0];
        for (int idx = tid; idx < 48 * (HP / 8); idx += 256) {
            int c = idx / (HP / 8);
            int k8 = (idx % (HP / 8)) * 8;
            int g = c / JT, jj = c % JT;
            *(uint4*)&Ws[c * WS_STRIDE + k8] =
                *(const uint4*)(src + ((size_t)g * HP + (j0 + jj)) * HP + k8);
        }
    }
    __syncthreads();

    const int arow  = m0w + (lane & 15);
    const uint32_t arb  = (uint32_t)arow * 128;
    const uint32_t axor = (uint32_t)(arow & 7) << 4;
    const uint32_t acl  = (uint32_t)(lane >> 4) << 4;

    const int b_row  = (lane >> 4) * 8 + (lane & 7);
    const int b_koff = ((lane >> 3) & 1) * 8;
    uint32_t wsp[3];
#pragma unroll
    for (int p = 0; p < 3; p++)
        wsp[p] = s2u(Ws) + ((p * 16 + b_row) * WS_STRIDE + b_koff) * 2;

    const size_t PLANE = (size_t)TB * HP;
    const float* __restrict__ GI0 = &g_GI[d][0][0][0];
    const float* __restrict__ bh0 = &g_bh[d][0][0];

    int ph[2] = {0, 0};
    float hreg[16];
#pragma unroll
    for (int i = 0; i < 16; i++) hreg[i] = 0.0f;

    for (int t = 0; t < Tt; t++) {
        const int p  = t & 1;
        const int xt = (d == 0) ? t : (Tt - 1 - t);
        const char* hcbase = (const char*)&g_hc[p][d][0][0][0];

        float acc[6][2][4];
#pragma unroll
        for (int nf = 0; nf < 6; nf++)
#pragma unroll
            for (int mi = 0; mi < 2; mi++)
#pragma unroll
                for (int i = 0; i < 4; i++) acc[nf][mi][i] = 0.0f;

        int nextI = 0;
        for (int kt = 0; kt < NCH; kt++) {
            while (nextI < NCH && nextI <= kt + 1) {
                if (tid == 0) {
                    const unsigned* cp = &g_hcnt[d][t][nextI];
                    while (ld_acq(cp) < 4u) __nanosleep(60);
                    const int st = nextI & 1;
                    const uint32_t mb = sb + st * 8;
                    expect_tx(mb, PCHUNK);
                    bulk_ld(sb + P_ABUF + st * PCHUNK,
                            hcbase + (size_t)nextI * PCHUNK, PCHUNK, mb);
                }
                nextI++;
            }
            const int st = kt & 1;
            MBAR_WAIT(sb + st * 8, ph[st]);
            ph[st] ^= 1;

            const uint32_t abuf = sb + P_ABUF + st * PCHUNK;
            const int k0 = kt * KC;
#pragma unroll
            for (int kk = 0; kk < 4; kk++) {
                const uint32_t ac = ((uint32_t)(kk * 32) + acl) ^ axor;
                uint32_t af[2][4];
                ldsm4(af[0], abuf + arb + ac);
                ldsm4(af[1], abuf + arb + 2048 + ac);
#pragma unroll
                for (int pg = 0; pg < 3; pg++) {
                    uint32_t bf[4];
                    ldsm4(bf, wsp[pg] + (k0 + kk * 16) * 2);
                    mma_fp16(acc[2 * pg][0],     af[0], bf);
                    mma_fp16(acc[2 * pg][1],     af[1], bf);
                    mma_fp16(acc[2 * pg + 1][0], af[0], bf + 2);
                    mma_fp16(acc[2 * pg + 1][1], af[1], bf + 2);
                }
            }
            __syncthreads();
        }

        // wait for this step's GI plane
        if (tid == 0) {
            while (ld_acq(&g_ready[d][xt]) == 0u) __nanosleep(100);
        }
        __syncthreads();

        // ---- fused GRU epilogue (h state in registers) ----
        const bool doOut = (t >= Cc) && (t < Tt - Cc);
        char* __restrict__ hco = (char*)&g_hc[p ^ 1][d][0][0][0];

#pragma unroll
        for (int mi = 0; mi < 2; mi++) {
#pragma unroll
            for (int nf0 = 0; nf0 < 2; nf0++) {
                const int jj = nf0 * 8 + tg * 2;
                const int j  = j0 + jj;
                const int jc = j & 63;
                const float br0 = bh0[j],            br1 = bh0[j + 1];
                const float bz0 = bh0[HP + j],       bz1 = bh0[HP + j + 1];
                const float bn0 = bh0[2 * HP + j],   bn1 = bh0[2 * HP + j + 1];
#pragma unroll
                for (int hf = 0; hf < 2; hf++) {
                    const int unit = ((mi * 2 + nf0) * 2 + hf) * 2;
                    const int b  = m0w + mi * 16 + grp + hf * 8;
                    const int ai = hf * 2;
                    const float aR0 = acc[nf0][mi][ai],     aR1 = acc[nf0][mi][ai + 1];
                    const float aZ0 = acc[nf0 + 2][mi][ai], aZ1 = acc[nf0 + 2][mi][ai + 1];
                    const float aN0 = acc[nf0 + 4][mi][ai], aN1 = acc[nf0 + 4][mi][ai + 1];

                    const size_t gio = (size_t)(xt * Bb + b) * HP + j;
                    const float gr0 = __ldcg(&GI0[gio]);
                    const float gr1 = __ldcg(&GI0[gio + 1]);
                    const float gz0 = __ldcg(&GI0[PLANE + gio]);
                    const float gz1 = __ldcg(&GI0[PLANE + gio + 1]);
                    const float gn0 = __ldcg(&GI0[2 * PLANE + gio]);
                    const float gn1 = __ldcg(&GI0[2 * PLANE + gio + 1]);

                    const float ho0 = hreg[unit];
                    const float ho1 = hreg[unit + 1];

                    const float r0 = sigf(gr0 + aR0 + br0);
                    const float r1 = sigf(gr1 + aR1 + br1);
                    const float z0 = sigf(gz0 + aZ0 + bz0);
                    const float z1 = sigf(gz1 + aZ1 + bz1);
                    const float n0 = tanh_fast(gn0 + r0 * (aN0 + bn0));
                    const float n1 = tanh_fast(gn1 + r1 * (aN1 + bn1));
                    const float h0 = (1.0f - z0) * n0 + z0 * ho0;
                    const float h1 = (1.0f - z1) * n1 + z1 * ho1;

                    hreg[unit]     = h0;
                    hreg[unit + 1] = h1;

                    size_t hoff = (size_t)chnk * PCHUNK + (size_t)b * 128
                                + ((unsigned)(jc * 2) ^ ((b & 7) << 4));
                    *(__half2*)(hco + hoff) = __floats2half2_rn(h0, h1);

                    if (doOut && j < Hh) {
                        const size_t xo = (size_t)b * Tt * WIN + (size_t)xt * WIN + j;
                        const size_t oo = (size_t)b * (OUTT * OUTW) + (size_t)(t - Cc) * OUTW + d * Hh + j;
                        out[oo]     = h0 + win[xo];
                        out[oo + 1] = h1 + win[xo + 1];
                    }
                }
            }
        }

        // publish own h-chunk contribution for step t+1
        __threadfence();
        __syncthreads();
        if (tid == 0) {
            asm volatile("red.release.gpu.global.add.u32 [%0], 1;"
                         :: "l"(&g_hcnt[d][t + 1][chnk]) : "memory");
        }
    }
}

// ---------------- launch ----------------
extern "C" void kernel_launch(void* const* d_in, const int* in_sizes, int n_in,
                              void* d_out, int out_size) {
    const float* windows = (const float*)d_in[0];
    const float* Wih_f   = (const float*)d_in[1];
    const float* Whh_f   = (const float*)d_in[2];
    const float* bih_f   = (const float*)d_in[3];
    const float* bhh_f   = (const float*)d_in[4];
    const float* Wih_b   = (const float*)d_in[5];
    const float* Whh_b   = (const float*)d_in[6];
    const float* bih_b   = (const float*)d_in[7];
    const float* bhh_b   = (const float*)d_in[8];
    float* out = (float*)d_out;

    static cudaStream_t s2 = nullptr;
    static cudaEvent_t  eA = nullptr, eH = nullptr, eB = nullptr;
    static int init_done = 0;
    if (!init_done) {
        cudaFuncSetAttribute(k_persist, cudaFuncAttributeMaxDynamicSharedMemorySize, P_SMEM);
        cudaFuncSetAttribute(k_gi, cudaFuncAttributeMaxDynamicSharedMemorySize, GI_SMEM);
        cudaStreamCreateWithFlags(&s2, cudaStreamNonBlocking);
        cudaEventCreateWithFlags(&eA, cudaEventDisableTiming);
        cudaEventCreateWithFlags(&eH, cudaEventDisableTiming);
        cudaEventCreateWithFlags(&eB, cudaEventDisableTiming);
        init_done = 1;
    }

    // side stream: x staging (k_gi input; same stream so ordered before k_gi)
    const int xtotal = TB * (HP / 4);
    prep_x<<<(xtotal + 255) / 256, 256, 0, s2>>>(windows);

    // main stream: weights + state init
    const int wthreads = 256;
    const int wtotal = 3 * HP * HP;
    prep_w<<<(wtotal + wthreads - 1) / wthreads, wthreads>>>(Wih_f, Whh_f, bih_f, bhh_f, 0);
    prep_w<<<(wtotal + wthreads - 1) / wthreads, wthreads>>>(Wih_b, Whh_b, bih_b, bhh_b, 1);
    const int ztotal = 2 * 2 * NCH * Bb * KC / 2;
    zero_h<<<(ztotal + 255) / 256, 256>>>();
    cudaEventRecord(eA, 0);

    // head: first HEADB steps' planes on the FULL chip (persist not yet launched)
    cudaStreamWaitEvent(s2, eA, 0);
    const int headY = 4 * HEADB;               // 384
    k_gi<<<dim3(18, headY), 256, GI_SMEM, s2>>>(0);
    cudaEventRecord(eH, s2);
    // tail: remaining planes, runs beside persist on leftover SMs
    k_gi<<<dim3(18, 4 * Tt - headY), 256, GI_SMEM, s2>>>(headY);
    cudaEventRecord(eB, s2);

    // persist starts once the head (buffer) is done
    cudaStreamWaitEvent(0, eH, 0);
    k_persist<<<NCTA, 256, P_SMEM>>>(windows, out);

    cudaStreamWaitEvent(0, eB, 0);
}

// round 16
// speedup vs baseline: 1.1933x; 1.1129x over previous
#include <cuda_runtime.h>
#include <cuda_fp16.h>
#include <cstdint>

#define Hh   744
#define HP   768
#define Bb   256
#define Tt   256
#define Cc   16
#define WIN  800
#define TB   (Tt*Bb)          // 65536
#define OUTT (Tt - 2*Cc)      // 224
#define OUTW (2*Hh)           // 1488

#define NJT    48
#define JT     16
#define NCTA   (2*NJT)
#define WS_STRIDE 776         // halfs: 768 + 8 pad
#define KC     64
#define NCH    (HP/KC)        // 12
#define PCHUNK 32768
#define GCHUNK 16384
#define UPP    36             // GI units per plane
#define QMAX   (2*Tt*UPP)     // 18432

// ---------------- scratch ----------------
__device__ __half g_Wic[6][NCH][HP][KC];
__device__ __half g_Wh16[2][3][HP][HP];
__device__ float  g_bi[2][3][HP];
__device__ float  g_bh[2][3][HP];
__device__ __half g_Xc[NCH][TB][KC];
__device__ float  g_GI[2][3][TB][HP];
__device__ __half g_hc[2][2][NCH][Bb][KC];
__device__ unsigned g_hcnt[2][Tt + 1][NCH];
__device__ unsigned g_ready[2][Tt];
__device__ unsigned g_pcnt[2][Tt];
__device__ unsigned g_q;

// ---------------- helpers ----------------
__device__ __forceinline__ float sigf(float x) { return 1.0f / (1.0f + __expf(-x)); }
__device__ __forceinline__ float tanh_fast(float x) {
    x = fminf(15.0f, fmaxf(-15.0f, x));
    float e = __expf(2.0f * x);
    return (e - 1.0f) / (e + 1.0f);
}
__device__ __forceinline__ void mma_fp16(float* c, const uint32_t* a, const uint32_t* b) {
    asm volatile(
        "mma.sync.aligned.m16n8k16.row.col.f32.f16.f16.f32 "
        "{%0,%1,%2,%3},{%4,%5,%6,%7},{%8,%9},{%0,%1,%2,%3};\n"
        : "+f"(c[0]), "+f"(c[1]), "+f"(c[2]), "+f"(c[3])
        : "r"(a[0]), "r"(a[1]), "r"(a[2]), "r"(a[3]), "r"(b[0]), "r"(b[1]));
}
__device__ __forceinline__ uint32_t s2u(const void* p) {
    return (uint32_t)__cvta_generic_to_shared(p);
}
__device__ __forceinline__ void ldsm4(uint32_t* r, uint32_t addr) {
    asm volatile("ldmatrix.sync.aligned.m8n8.x4.shared.b16 {%0,%1,%2,%3}, [%4];"
        : "=r"(r[0]), "=r"(r[1]), "=r"(r[2]), "=r"(r[3]) : "r"(addr));
}
#define MBAR_INIT(addr, cnt) \
    asm volatile("mbarrier.init.shared.b64 [%0], %1;" :: "r"(addr), "r"(cnt) : "memory")
#define MBAR_WAIT(addr, par) do { \
    asm volatile("{.reg .pred P1; WL%=: mbarrier.try_wait.parity.acquire.cta.shared::cta.b64 P1, [%0], %1, 0x989680; @P1 bra.uni WD%=; bra.uni WL%=; WD%=:}" \
        :: "r"(addr), "r"(par) : "memory"); \
} while (0)
__device__ __forceinline__ void bulk_ld(uint32_t dst, const void* src, uint32_t bytes, uint32_t mb) {
    asm volatile("cp.async.bulk.shared::cta.global.mbarrier::complete_tx::bytes [%0], [%1], %2, [%3];"
        :: "r"(dst), "l"(src), "r"(bytes), "r"(mb) : "memory");
}
__device__ __forceinline__ void expect_tx(uint32_t mb, uint32_t bytes) {
    asm volatile("mbarrier.arrive.expect_tx.shared.b64 _, [%0], %1;"
        :: "r"(mb), "r"(bytes) : "memory");
}
__device__ __forceinline__ unsigned ld_acq(const unsigned* p) {
    unsigned v;
    asm volatile("ld.acquire.gpu.global.u32 %0, [%1];" : "=r"(v) : "l"(p));
    return v;
}

// ---------------- prep kernels ----------------
__global__ void prep_w(const float* __restrict__ Wih, const float* __restrict__ Whh,
                       const float* __restrict__ bih, const float* __restrict__ bhh, int d) {
    int idx = blockIdx.x * blockDim.x + threadIdx.x;
    const int total = 3 * HP * HP;
    if (idx < total) {
        int g = idx / (HP * HP);
        int rem = idx % (HP * HP);
        int j = rem / HP;
        int k = rem % HP;
        float wi = 0.0f, wh = 0.0f;
        if (j < Hh && k < Hh) {
            wi = Wih[(size_t)(g * Hh + j) * Hh + k];
            wh = Whh[(size_t)(g * Hh + j) * Hh + k];
        }
        int dg = d * 3 + g;
        int ch = k / KC, kc = k % KC;
        size_t off = (((size_t)dg * NCH + ch) * HP + j) * 128 + (((unsigned)(kc * 2)) ^ ((j & 7) << 4));
        *(__half*)((char*)g_Wic + off) = __float2half_rn(wi);
        g_Wh16[d][g][j][k] = __float2half_rn(wh);
    }
    if (idx < 3 * HP) {
        int g = idx / HP, j = idx % HP;
        float bi = 0.0f, bh = 0.0f;
        if (j < Hh) { bi = bih[g * Hh + j]; bh = bhh[g * Hh + j]; }
        g_bi[d][g][j] = bi;
        g_bh[d][g][j] = bh;
    }
}

__global__ void prep_x(const float* __restrict__ win) {
    int idx = blockIdx.x * blockDim.x + threadIdx.x;
    const int total = TB * (HP / 4);
    if (idx >= total) return;
    int row = idx / (HP / 4);
    int kq  = idx % (HP / 4);
    int k = kq * 4;
    int t = row / Bb, b = row % Bb;
    float4 v = make_float4(0.f, 0.f, 0.f, 0.f);
    if (k < Hh) {
        v = *(const float4*)(win + (size_t)b * Tt * WIN + (size_t)t * WIN + k);
    }
    int ch = k / KC, kc = k % KC;
    size_t off = ((size_t)ch * TB + row) * 128 + (((unsigned)(kc * 2)) ^ ((row & 7) << 4));
    __half2* dst = (__half2*)((char*)g_Xc + off);
    dst[0] = __floats2half2_rn(v.x, v.y);
    dst[1] = __floats2half2_rn(v.z, v.w);
}

__global__ void zero_h() {
    int idx = blockIdx.x * blockDim.x + threadIdx.x;
    const int hcu32 = 2 * 2 * NCH * Bb * KC / 2;
    if (idx < hcu32) ((uint32_t*)g_hc)[idx] = 0u;
    const int hcnt_total = 2 * (Tt + 1) * NCH;
    if (idx < hcnt_total) {
        int within = idx % ((Tt + 1) * NCH);
        int step = within / NCH;
        ((unsigned*)g_hcnt)[idx] = (step == 0) ? 4u : 0u;
    }
    if (idx < 2 * Tt) { ((unsigned*)g_ready)[idx] = 0u; ((unsigned*)g_pcnt)[idx] = 0u; }
    if (idx == 0) g_q = 0u;
}

// ---------------- GI unit processor (one 128M x 128N x 768K tile) ----------------
// smem contract (both callers): mbars at sb+16 / sb+24 (kernel-lifetime phases in
// sph[2]); two 32KB stages at sb+1024 and sb+1024+32768 (X at +0, W at +16384),
// quiescent on entry. Unit u -> plane order e=u/36 (d=e&1, tc=e>>1), rest: halfb,
// g, nt. Ends with all warps synced and stages quiescent.
__device__ __forceinline__ void gi_unit(int u, uint32_t sb, int* sph) {
    const int tid  = threadIdx.x;
    const int lane = tid & 31;
    const int w    = tid >> 5;
    const int grp  = lane >> 2;
    const int tg   = lane & 3;
    const int wm   = w >> 1;
    const int wn   = w & 1;

    const int e     = u / UPP;
    const int rest  = u % UPP;
    const int halfb = rest / 18;
    const int cfg   = rest % 18;
    const int g     = cfg / 6;
    const int nt    = cfg % 6;
    const int d     = e & 1;
    const int tc    = e >> 1;
    const int t     = d ? (Tt - 1 - tc) : tc;
    const int j0    = nt * 128;
    const int dg    = d * 3 + g;
    const int row0  = t * Bb + halfb * 128;

    const int arow  = wm * 32 + (lane & 15);
    const uint32_t arb  = (uint32_t)arow * 128;
    const uint32_t axor = (uint32_t)(arow & 7) << 4;
    const uint32_t acl  = (uint32_t)(lane >> 4) << 4;
    const int brow  = wn * 64 + (lane >> 4) * 8 + (lane & 7);
    const uint32_t brb  = (uint32_t)brow * 128;
    const uint32_t bxor = (uint32_t)(brow & 7) << 4;
    const uint32_t bcl  = (uint32_t)((lane >> 3) & 1) << 4;

    float acc[8][2][4];
#pragma unroll
    for (int nf = 0; nf < 8; nf++)
#pragma unroll
        for (int mi = 0; mi < 2; mi++)
#pragma unroll
            for (int i = 0; i < 4; i++) acc[nf][mi][i] = 0.0f;

    auto issue = [&](int c) {
        if (tid == 0) {
            const int s = c & 1;
            const uint32_t mb = sb + 16 + s * 8;
            expect_tx(mb, 2 * GCHUNK);
            bulk_ld(sb + 1024 + s * 32768,
                    (const char*)g_Xc + ((size_t)c * TB + row0) * 128, GCHUNK, mb);
            bulk_ld(sb + 1024 + s * 32768 + GCHUNK,
                    (const char*)g_Wic + (((size_t)dg * NCH + c) * HP + j0) * 128, GCHUNK, mb);
        }
    };

    issue(0);
    for (int kt = 0; kt < NCH; kt++) {
        const int s = kt & 1;
        if (kt < NCH - 1) issue(kt + 1);
        MBAR_WAIT(sb + 16 + s * 8, sph[s]);
        sph[s] ^= 1;

        const uint32_t abuf = sb + 1024 + s * 32768;
        const uint32_t bbuf = abuf + GCHUNK;
#pragma unroll
        for (int kk = 0; kk < 4; kk++) {
            const uint32_t ac = ((uint32_t)(kk * 32) + acl) ^ axor;
            const uint32_t bc = ((uint32_t)(kk * 32) + bcl) ^ bxor;
            uint32_t af[2][4];
            ldsm4(af[0], abuf + arb + ac);
            ldsm4(af[1], abuf + arb + 2048 + ac);
#pragma unroll
            for (int p = 0; p < 4; p++) {
                uint32_t bf[4];
                ldsm4(bf, bbuf + brb + p * 2048 + bc);
                mma_fp16(acc[2 * p][0],     af[0], bf);
                mma_fp16(acc[2 * p][1],     af[1], bf);
                mma_fp16(acc[2 * p + 1][0], af[0], bf + 2);
                mma_fp16(acc[2 * p + 1][1], af[1], bf + 2);
            }
        }
        __syncthreads();
    }

    float* __restrict__ GIp = &g_GI[d][g][0][0];
    const float* __restrict__ bip = &g_bi[d][g][0];
#pragma unroll
    for (int mi = 0; mi < 2; mi++) {
#pragma unroll
        for (int nf = 0; nf < 8; nf++) {
            int r = row0 + wm * 32 + mi * 16 + grp;
            int j = j0 + wn * 64 + nf * 8 + tg * 2;
            float b0 = bip[j], b1 = bip[j + 1];
            float* a = acc[nf][mi];
            GIp[(size_t)r * HP + j]           = a[0] + b0;
            GIp[(size_t)r * HP + j + 1]       = a[1] + b1;
            GIp[(size_t)(r + 8) * HP + j]     = a[2] + b0;
            GIp[(size_t)(r + 8) * HP + j + 1] = a[3] + b1;
        }
    }

    __threadfence();
    __syncthreads();
    if (tid == 0) {
        unsigned old = atomicAdd(&g_pcnt[d][t], 1u);
        if (old == UPP - 1) {
            asm volatile("st.release.gpu.global.u32 [%0], %1;"
                         :: "l"(&g_ready[d][t]), "r"(1u) : "memory");
        }
    }
}

// ---------------- persistent GI helper: drains the queue on free SMs ----------------
#define GI_SMEM (1024 + 2 * PCHUNK)   // 66560
__global__ void __launch_bounds__(256, 2) k_gihelp() {
    extern __shared__ __align__(1024) char smem[];
    const uint32_t sb = s2u(smem);
    __shared__ int cmd_s;

    if (threadIdx.x == 0) { MBAR_INIT(sb + 16, 1); MBAR_INIT(sb + 24, 1); }
    __syncthreads();

    int sph[2] = {0, 0};
    while (true) {
        if (threadIdx.x == 0) {
            unsigned u = atomicAdd(&g_q, 1u);
            cmd_s = (u < QMAX) ? (int)u : -1;
        }
        __syncthreads();
        const int cmd = cmd_s;
        __syncthreads();
        if (cmd < 0) return;
        gi_unit(cmd, sb, sph);
    }
}

// ---------------- persistent recurrent kernel with GI work stealing ----------------
// smem: mbar h0/h1 @0/8, steal mbars @16/24 | 1024: stages 2x32KB | 66560: Ws
#define P_ABUF  1024
#define P_WSOFF (P_ABUF + 2 * PCHUNK)
#define P_SMEM  (P_WSOFF + 48 * WS_STRIDE * 2)   // 141056
__global__ void __launch_bounds__(256, 2)
k_persist(const float* __restrict__ win, float* __restrict__ out) {
    extern __shared__ __align__(1024) char smem[];
    const uint32_t sb = s2u(smem);
    __half* Ws = (__half*)(smem + P_WSOFF);
    __shared__ int cmd_s;

    const int tid  = threadIdx.x;
    const int lane = tid & 31;
    const int w    = tid >> 5;
    const int grp  = lane >> 2;
    const int tg   = lane & 3;
    const int m0w  = w * 32;

    const int d    = blockIdx.x / NJT;
    const int j0   = (blockIdx.x % NJT) * JT;
    const int chnk = j0 >> 6;

    if (tid == 0) {
        MBAR_INIT(sb, 1); MBAR_INIT(sb + 8, 1);
        MBAR_INIT(sb + 16, 1); MBAR_INIT(sb + 24, 1);
    }

    {
        const __half* src = &g_Wh16[d][0][0][0];
        for (int idx = tid; idx < 48 * (HP / 8); idx += 256) {
            int c = idx / (HP / 8);
            int k8 = (idx % (HP / 8)) * 8;
            int g = c / JT, jj = c % JT;
            *(uint4*)&Ws[c * WS_STRIDE + k8] =
                *(const uint4*)(src + ((size_t)g * HP + (j0 + jj)) * HP + k8);
        }
    }
    __syncthreads();

    const int arow  = m0w + (lane & 15);
    const uint32_t arb  = (uint32_t)arow * 128;
    const uint32_t axor = (uint32_t)(arow & 7) << 4;
    const uint32_t acl  = (uint32_t)(lane >> 4) << 4;

    const int b_row  = (lane >> 4) * 8 + (lane & 7);
    const int b_koff = ((lane >> 3) & 1) * 8;
    uint32_t wsp[3];
#pragma unroll
    for (int p = 0; p < 3; p++)
        wsp[p] = s2u(Ws) + ((p * 16 + b_row) * WS_STRIDE + b_koff) * 2;

    const size_t PLANE = (size_t)TB * HP;
    const float* __restrict__ GI0 = &g_GI[d][0][0][0];
    const float* __restrict__ bh0 = &g_bh[d][0][0];

    int ph[2] = {0, 0};
    int sph[2] = {0, 0};
    float hreg[16];
#pragma unroll
    for (int i = 0; i < 16; i++) hreg[i] = 0.0f;

    for (int t = 0; t < Tt; t++) {
        const int p  = t & 1;
        const int xt = (d == 0) ? t : (Tt - 1 - t);
        const char* hcbase = (const char*)&g_hc[p][d][0][0][0];

        float acc[6][2][4];
#pragma unroll
        for (int nf = 0; nf < 6; nf++)
#pragma unroll
            for (int mi = 0; mi < 2; mi++)
#pragma unroll
                for (int i = 0; i < 4; i++) acc[nf][mi][i] = 0.0f;

        int nextI = 0;
        for (int kt = 0; kt < NCH; kt++) {
            while (nextI < NCH && nextI <= kt + 1) {
                if (tid == 0) {
                    const unsigned* cp = &g_hcnt[d][t][nextI];
                    while (ld_acq(cp) < 4u) __nanosleep(60);
                    const int st = nextI & 1;
                    const uint32_t mb = sb + st * 8;
                    expect_tx(mb, PCHUNK);
                    bulk_ld(sb + P_ABUF + st * PCHUNK,
                            hcbase + (size_t)nextI * PCHUNK, PCHUNK, mb);
                }
                nextI++;
            }
            const int st = kt & 1;
            MBAR_WAIT(sb + st * 8, ph[st]);
            ph[st] ^= 1;

            const uint32_t abuf = sb + P_ABUF + st * PCHUNK;
            const int k0 = kt * KC;
#pragma unroll
            for (int kk = 0; kk < 4; kk++) {
                const uint32_t ac = ((uint32_t)(kk * 32) + acl) ^ axor;
                uint32_t af[2][4];
                ldsm4(af[0], abuf + arb + ac);
                ldsm4(af[1], abuf + arb + 2048 + ac);
#pragma unroll
                for (int pg = 0; pg < 3; pg++) {
                    uint32_t bf[4];
                    ldsm4(bf, wsp[pg] + (k0 + kk * 16) * 2);
                    mma_fp16(acc[2 * pg][0],     af[0], bf);
                    mma_fp16(acc[2 * pg][1],     af[1], bf);
                    mma_fp16(acc[2 * pg + 1][0], af[0], bf + 2);
                    mma_fp16(acc[2 * pg + 1][1], af[1], bf + 2);
                }
            }
            __syncthreads();
        }

        // ---- steal GI work while this step's plane isn't ready ----
        while (true) {
            if (tid == 0) {
                int c;
                if (ld_acq(&g_ready[d][xt]) != 0u) c = -1;
                else {
                    unsigned u = atomicAdd(&g_q, 1u);
                    c = (u < QMAX) ? (int)u : -2;
                }
                cmd_s = c;
            }
            __syncthreads();
            const int cmd = cmd_s;
            __syncthreads();
            if (cmd == -1) break;
            if (cmd == -2) {
                // queue drained; plain wait
                if (tid == 0) {
                    while (ld_acq(&g_ready[d][xt]) == 0u) __nanosleep(100);
                }
                __syncthreads();
                break;
            }
            gi_unit(cmd, sb, sph);
        }

        // ---- fused GRU epilogue (h state in registers) ----
        const bool doOut = (t >= Cc) && (t < Tt - Cc);
        char* __restrict__ hco = (char*)&g_hc[p ^ 1][d][0][0][0];

#pragma unroll
        for (int mi = 0; mi < 2; mi++) {
#pragma unroll
            for (int nf0 = 0; nf0 < 2; nf0++) {
                const int jj = nf0 * 8 + tg * 2;
                const int j  = j0 + jj;
                const int jc = j & 63;
                const float br0 = bh0[j],            br1 = bh0[j + 1];
                const float bz0 = bh0[HP + j],       bz1 = bh0[HP + j + 1];
                const float bn0 = bh0[2 * HP + j],   bn1 = bh0[2 * HP + j + 1];
#pragma unroll
                for (int hf = 0; hf < 2; hf++) {
                    const int unit = ((mi * 2 + nf0) * 2 + hf) * 2;
                    const int b  = m0w + mi * 16 + grp + hf * 8;
                    const int ai = hf * 2;
                    const float aR0 = acc[nf0][mi][ai],     aR1 = acc[nf0][mi][ai + 1];
                    const float aZ0 = acc[nf0 + 2][mi][ai], aZ1 = acc[nf0 + 2][mi][ai + 1];
                    const float aN0 = acc[nf0 + 4][mi][ai], aN1 = acc[nf0 + 4][mi][ai + 1];

                    const size_t gio = (size_t)(xt * Bb + b) * HP + j;
                    const float gr0 = __ldcg(&GI0[gio]);
                    const float gr1 = __ldcg(&GI0[gio + 1]);
                    const float gz0 = __ldcg(&GI0[PLANE + gio]);
                    const float gz1 = __ldcg(&GI0[PLANE + gio + 1]);
                    const float gn0 = __ldcg(&GI0[2 * PLANE + gio]);
                    const float gn1 = __ldcg(&GI0[2 * PLANE + gio + 1]);

                    const float ho0 = hreg[unit];
                    const float ho1 = hreg[unit + 1];

                    const float r0 = sigf(gr0 + aR0 + br0);
                    const float r1 = sigf(gr1 + aR1 + br1);
                    const float z0 = sigf(gz0 + aZ0 + bz0);
                    const float z1 = sigf(gz1 + aZ1 + bz1);
                    const float n0 = tanh_fast(gn0 + r0 * (aN0 + bn0));
                    const float n1 = tanh_fast(gn1 + r1 * (aN1 + bn1));
                    const float h0 = (1.0f - z0) * n0 + z0 * ho0;
                    const float h1 = (1.0f - z1) * n1 + z1 * ho1;

                    hreg[unit]     = h0;
                    hreg[unit + 1] = h1;

                    size_t hoff = (size_t)chnk * PCHUNK + (size_t)b * 128
                                + ((unsigned)(jc * 2) ^ ((b & 7) << 4));
                    *(__half2*)(hco + hoff) = __floats2half2_rn(h0, h1);

                    if (doOut && j < Hh) {
                        const size_t xo = (size_t)b * Tt * WIN + (size_t)xt * WIN + j;
                        const size_t oo = (size_t)b * (OUTT * OUTW) + (size_t)(t - Cc) * OUTW + d * Hh + j;
                        out[oo]     = h0 + win[xo];
                        out[oo + 1] = h1 + win[xo + 1];
                    }
                }
            }
        }

        // publish own h-chunk contribution for step t+1
        __threadfence();
        __syncthreads();
        if (tid == 0) {
            asm volatile("red.release.gpu.global.add.u32 [%0], 1;"
                         :: "l"(&g_hcnt[d][t + 1][chnk]) : "memory");
        }
    }
}

// ---------------- launch ----------------
extern "C" void kernel_launch(void* const* d_in, const int* in_sizes, int n_in,
                              void* d_out, int out_size) {
    const float* windows = (const float*)d_in[0];
    const float* Wih_f   = (const float*)d_in[1];
    const float* Whh_f   = (const float*)d_in[2];
    const float* bih_f   = (const float*)d_in[3];
    const float* bhh_f   = (const float*)d_in[4];
    const float* Wih_b   = (const float*)d_in[5];
    const float* Whh_b   = (const float*)d_in[6];
    const float* bih_b   = (const float*)d_in[7];
    const float* bhh_b   = (const float*)d_in[8];
    float* out = (float*)d_out;

    static cudaStream_t s2 = nullptr;
    static cudaEvent_t  eA = nullptr, eB = nullptr;
    static int init_done = 0;
    if (!init_done) {
        cudaFuncSetAttribute(k_persist, cudaFuncAttributeMaxDynamicSharedMemorySize, P_SMEM);
        cudaFuncSetAttribute(k_gihelp, cudaFuncAttributeMaxDynamicSharedMemorySize, GI_SMEM);
        cudaStreamCreateWithFlags(&s2, cudaStreamNonBlocking);
        cudaEventCreateWithFlags(&eA, cudaEventDisableTiming);
        cudaEventCreateWithFlags(&eB, cudaEventDisableTiming);
        init_done = 1;
    }

    // ALL prep on the origin stream (legal capture ordering; persist thieves
    // and the helper both need g_Xc/g_Wic/g_hc before starting)
    const int wthreads = 256;
    const int wtotal = 3 * HP * HP;
    prep_w<<<(wtotal + wthreads - 1) / wthreads, wthreads>>>(Wih_f, Whh_f, bih_f, bhh_f, 0);
    prep_w<<<(wtotal + wthreads - 1) / wthreads, wthreads>>>(Wih_b, Whh_b, bih_b, bhh_b, 1);
    const int xtotal = TB * (HP / 4);
    prep_x<<<(xtotal + 255) / 256, 256>>>(windows);
    const int ztotal = 2 * 2 * NCH * Bb * KC / 2;
    zero_h<<<(ztotal + 255) / 256, 256>>>();
    cudaEventRecord(eA, 0);

    // persist first (claims 96 SMs; steals GI units while waiting on planes)
    k_persist<<<NCTA, 256, P_SMEM>>>(windows, out);

    // helper drains the queue on the remaining SMs (joins capture via eA)
    cudaStreamWaitEvent(s2, eA, 0);
    k_gihelp<<<104, 256, GI_SMEM, s2>>>();
    cudaEventRecord(eB, s2);

    cudaStreamWaitEvent(0, eB, 0);
}